// round 8
// baseline (speedup 1.0000x reference)
#include <cuda_runtime.h>
#include <cstdint>

// out[tok, :] = sum_{l=0..7} weight[l, x[tok, l], :]
//   x:      16384 tokens x 8 int32 indices
//   weight: (8, 1024, 1024) f32, 32 MB (L2-resident)
//   out:    16384 x 1024 f32
//
// One CTA per token, 128 threads; each thread owns TWO float4 columns
// (tid, tid+128) -> 16 independent LDG.128 in flight per thread (2x MLP of
// the 256-thread version), halving per-byte instruction overhead.

static constexpr int NTOK = 8 * 2048;   // 16384
static constexpr int K    = 1024;
static constexpr int D4   = 1024 / 4;   // 256 float4 per row

__device__ __forceinline__ float4 ldg_evict_last(const float4* p)
{
    float4 v;
    asm volatile("ld.global.nc.L1::evict_last.v4.f32 {%0, %1, %2, %3}, [%4];"
                 : "=f"(v.x), "=f"(v.y), "=f"(v.z), "=f"(v.w)
                 : "l"(p));
    return v;
}

__device__ __forceinline__ void add4(float4& a, const float4 b)
{
    a.x += b.x; a.y += b.y; a.z += b.z; a.w += b.w;
}

__global__ __launch_bounds__(128, 16)
void multi_embed_kernel(const int4* __restrict__ x4,
                        const float4* __restrict__ w,
                        float4* __restrict__ out)
{
    const int tok = blockIdx.x;
    const int tid = threadIdx.x;

    // All 8 indices via two uniform 16B loads (warp-broadcast).
    const int4 iA = __ldg(x4 + tok * 2);       // l = 0..3
    const int4 iB = __ldg(x4 + tok * 2 + 1);   // l = 4..7

    size_t r0 = (size_t)(0 * K + iA.x) * D4;
    size_t r1 = (size_t)(1 * K + iA.y) * D4;
    size_t r2 = (size_t)(2 * K + iA.z) * D4;
    size_t r3 = (size_t)(3 * K + iA.w) * D4;
    size_t r4 = (size_t)(4 * K + iB.x) * D4;
    size_t r5 = (size_t)(5 * K + iB.y) * D4;
    size_t r6 = (size_t)(6 * K + iB.z) * D4;
    size_t r7 = (size_t)(7 * K + iB.w) * D4;

    const float4* wt0 = w + tid;         // columns [tid*4 .. tid*4+3]
    const float4* wt1 = w + tid + 128;   // columns [(tid+128)*4 ..]

    // 16 independent LDG.128 front-batched, evict_last in L1.
    float4 a0 = ldg_evict_last(wt0 + r0);
    float4 a1 = ldg_evict_last(wt0 + r1);
    float4 a2 = ldg_evict_last(wt0 + r2);
    float4 a3 = ldg_evict_last(wt0 + r3);
    float4 a4 = ldg_evict_last(wt0 + r4);
    float4 a5 = ldg_evict_last(wt0 + r5);
    float4 a6 = ldg_evict_last(wt0 + r6);
    float4 a7 = ldg_evict_last(wt0 + r7);

    float4 c0 = ldg_evict_last(wt1 + r0);
    float4 c1 = ldg_evict_last(wt1 + r1);
    float4 c2 = ldg_evict_last(wt1 + r2);
    float4 c3 = ldg_evict_last(wt1 + r3);
    float4 c4 = ldg_evict_last(wt1 + r4);
    float4 c5 = ldg_evict_last(wt1 + r5);
    float4 c6 = ldg_evict_last(wt1 + r6);
    float4 c7 = ldg_evict_last(wt1 + r7);

    float4 accA = a0;
    add4(accA, a1); add4(accA, a2); add4(accA, a3);
    add4(accA, a4); add4(accA, a5); add4(accA, a6); add4(accA, a7);

    float4 accC = c0;
    add4(accC, c1); add4(accC, c2); add4(accC, c3);
    add4(accC, c4); add4(accC, c5); add4(accC, c6); add4(accC, c7);

    // Streaming stores: evict-first, don't displace weight lines.
    float4* dst = out + (size_t)tok * D4;
    asm volatile("st.global.cs.v4.f32 [%0], {%1, %2, %3, %4};"
                 :: "l"(dst + tid),
                    "f"(accA.x), "f"(accA.y), "f"(accA.z), "f"(accA.w)
                 : "memory");
    asm volatile("st.global.cs.v4.f32 [%0], {%1, %2, %3, %4};"
                 :: "l"(dst + tid + 128),
                    "f"(accC.x), "f"(accC.y), "f"(accC.z), "f"(accC.w)
                 : "memory");
}

extern "C" void kernel_launch(void* const* d_in, const int* in_sizes, int n_in,
                              void* d_out, int out_size)
{
    const int4*   x = (const int4*)d_in[0];
    const float4* w = (const float4*)d_in[1];
    float4*       o = (float4*)d_out;

    multi_embed_kernel<<<NTOK, 128>>>(x, w, o);
}